// round 2
// baseline (speedup 1.0000x reference)
#include <cuda_runtime.h>
#include <cuda_bf16.h>

#define N_NODES 1024
#define D_EMB 64
#define F_IN 128
#define H_DIM 64
#define N_CLS 8

// Scratch (no cudaMalloc allowed)
__device__ float g_a[N_NODES * H_DIM];     // embed @ W1[:64] + b1
__device__ float g_b[N_NODES * H_DIM];     // embed @ W1[64:]
__device__ float g_xw[N_NODES * H_DIM];    // x @ Wg1
__device__ float g_gate[N_NODES * N_NODES];
__device__ float g_hg[N_NODES * H_DIM];    // relu(masked_adj @ xw)

// ---------------------------------------------------------------------------
// Kernel 1: per-node precompute. 128 blocks x 64 threads, 8 rows per block.
// ---------------------------------------------------------------------------
__global__ __launch_bounds__(64) void prep_kernel(
    const float* __restrict__ embed, const float* __restrict__ x,
    const float* __restrict__ W1, const float* __restrict__ b1,
    const float* __restrict__ Wg1)
{
    __shared__ float se[8 * D_EMB];
    __shared__ float sx[8 * F_IN];
    const int t = threadIdx.x;            // 0..63 = output column
    const int i0 = blockIdx.x * 8;

    #pragma unroll
    for (int p = 0; p < 8; p++)  se[t + p * 64] = embed[i0 * D_EMB + t + p * 64];
    #pragma unroll
    for (int p = 0; p < 16; p++) sx[t + p * 64] = x[i0 * F_IN + t + p * 64];
    __syncthreads();

    float va[8], vb[8], vx[8];
    const float bias = b1[t];
    #pragma unroll
    for (int r = 0; r < 8; r++) { va[r] = bias; vb[r] = 0.f; vx[r] = 0.f; }

    #pragma unroll 4
    for (int k = 0; k < D_EMB; k++) {
        const float w1a = W1[k * H_DIM + t];
        const float w1b = W1[(D_EMB + k) * H_DIM + t];
        #pragma unroll
        for (int r = 0; r < 8; r++) {
            const float e = se[r * D_EMB + k];
            va[r] = fmaf(e, w1a, va[r]);
            vb[r] = fmaf(e, w1b, vb[r]);
        }
    }
    #pragma unroll 4
    for (int k = 0; k < F_IN; k++) {
        const float wg = Wg1[k * H_DIM + t];
        #pragma unroll
        for (int r = 0; r < 8; r++)
            vx[r] = fmaf(sx[r * F_IN + k], wg, vx[r]);
    }
    #pragma unroll
    for (int r = 0; r < 8; r++) {
        g_a [(i0 + r) * H_DIM + t] = va[r];
        g_b [(i0 + r) * H_DIM + t] = vb[r];
        g_xw[(i0 + r) * H_DIM + t] = vx[r];
    }
}

// ---------------------------------------------------------------------------
// Kernel 2: per-edge gate. Grid (32,32), block 256; each block = 32x32 edges,
// each thread a 2x2 micro-tile. smem stored transposed [k][row], pad 33.
// ---------------------------------------------------------------------------
__device__ __forceinline__ float gate_of(float u, float la, float invb)
{
    // sigmoid((log(u) - log(1-u) + la) / beta)
    const float z = (__logf(u) - __logf(1.f - u) + la) * invb;
    return __frcp_rn(1.f + __expf(-z));
}

__global__ __launch_bounds__(256) void edge_kernel(
    const float* __restrict__ noise, const float* __restrict__ W2,
    const float* __restrict__ b2, const float* __restrict__ tmp)
{
    __shared__ float sa[64 * 33];
    __shared__ float sb[64 * 33];
    __shared__ float sw2[64];

    const int t  = threadIdx.x;
    const int i0 = blockIdx.y * 32;
    const int j0 = blockIdx.x * 32;

    // load 32 rows x 64 cols of g_a / g_b, transposed into [k][r] (pad 33)
    #pragma unroll
    for (int p = 0; p < 8; p++) {
        const int idx = t + p * 256;
        const int r = idx >> 6;          // 0..31
        const int k = idx & 63;          // 0..63
        sa[k * 33 + r] = g_a[(i0 + r) * H_DIM + k];
        sb[k * 33 + r] = g_b[(j0 + r) * H_DIM + k];
    }
    if (t < 64) sw2[t] = W2[t];
    __syncthreads();

    const int tx = t & 15, ty = t >> 4;
    const float b2s = b2[0];
    float la00 = b2s, la01 = b2s, la10 = b2s, la11 = b2s;

    #pragma unroll
    for (int k = 0; k < 64; k++) {
        const float a0 = sa[k * 33 + 2 * ty];
        const float a1 = sa[k * 33 + 2 * ty + 1];
        const float bx = sb[k * 33 + 2 * tx];
        const float by = sb[k * 33 + 2 * tx + 1];
        const float w = sw2[k];
        la00 = fmaf(fmaxf(a0 + bx, 0.f), w, la00);
        la01 = fmaf(fmaxf(a0 + by, 0.f), w, la01);
        la10 = fmaf(fmaxf(a1 + bx, 0.f), w, la10);
        la11 = fmaf(fmaxf(a1 + by, 0.f), w, la11);
    }

    const float invb = __frcp_rn(tmp[0]);
    const int i = i0 + 2 * ty;
    const int j = j0 + 2 * tx;

    const float2 u0 = *(const float2*)&noise[(size_t)i * N_NODES + j];
    const float2 u1 = *(const float2*)&noise[(size_t)(i + 1) * N_NODES + j];

    float2 o0, o1;
    o0.x = gate_of(u0.x, la00, invb);
    o0.y = gate_of(u0.y, la01, invb);
    o1.x = gate_of(u1.x, la10, invb);
    o1.y = gate_of(u1.y, la11, invb);
    *(float2*)&g_gate[(size_t)i * N_NODES + j]       = o0;
    *(float2*)&g_gate[(size_t)(i + 1) * N_NODES + j] = o1;
}

// ---------------------------------------------------------------------------
// Kernel 3: hg = relu( (adj .* 0.5*(G+G^T)) @ xw ). 128 blocks x 256 thr,
// each block owns 8 rows x 64 cols, k tiled by 64, mask built in smem.
// ---------------------------------------------------------------------------
__global__ __launch_bounds__(256) void spmm_kernel(const float* __restrict__ adj)
{
    __shared__ float s_ah[8 * 64];                  // 0.5 * adj tile
    __shared__ float s_m [8 * 64];                  // masked-adj tile
    __shared__ __align__(16) float s_xw[64 * 64];   // xw k-tile

    const int t  = threadIdx.x;
    const int i0 = blockIdx.x * 8;
    const int f2 = (t & 31) * 2;     // 2 adjacent output cols
    const int rr = t >> 5;           // row 0..7

    float acc0 = 0.f, acc1 = 0.f;

    for (int k0 = 0; k0 < N_NODES; k0 += 64) {
        __syncthreads();
        // adj + forward-gate part of mask, and xw tile
        #pragma unroll
        for (int p = 0; p < 2; p++) {
            const int idx = t + p * 256;
            const int r = idx >> 6, k = idx & 63;
            const float av = 0.5f * adj[(size_t)(i0 + r) * N_NODES + k0 + k];
            s_ah[r * 64 + k] = av;
            s_m [r * 64 + k] = av * g_gate[(size_t)(i0 + r) * N_NODES + k0 + k];
        }
        #pragma unroll
        for (int p = 0; p < 16; p++) {
            const int idx = t + p * 256;
            const int k = idx >> 6, f = idx & 63;
            s_xw[k * 64 + f] = g_xw[(k0 + k) * H_DIM + f];
        }
        __syncthreads();
        // transposed-gate part: G[k][i]
        #pragma unroll
        for (int p = 0; p < 2; p++) {
            const int idx = t + p * 256;
            const int k = idx >> 3, r = idx & 7;
            s_m[r * 64 + k] += s_ah[r * 64 + k] *
                               g_gate[(size_t)(k0 + k) * N_NODES + i0 + r];
        }
        __syncthreads();

        #pragma unroll
        for (int k = 0; k < 64; k++) {
            const float mv  = s_m[rr * 64 + k];
            const float2 xv = *(const float2*)&s_xw[k * 64 + f2];
            acc0 = fmaf(mv, xv.x, acc0);
            acc1 = fmaf(mv, xv.y, acc1);
        }
    }
    g_hg[(i0 + rr) * H_DIM + f2]     = fmaxf(acc0, 0.f);
    g_hg[(i0 + rr) * H_DIM + f2 + 1] = fmaxf(acc1, 0.f);
}

// ---------------------------------------------------------------------------
// Kernel 4: mean-pool + logits + softmax. One block, 256 threads.
// ---------------------------------------------------------------------------
__global__ __launch_bounds__(256) void final_kernel(
    const float* __restrict__ Wg2, float* __restrict__ out)
{
    __shared__ float sred[256];
    __shared__ float sp[64];
    __shared__ float slog[8];
    __shared__ float sexp[8];

    const int t = threadIdx.x;
    const int f = t & 63, c = t >> 6;
    float s = 0.f;
    for (int i = c * 256; i < c * 256 + 256; i++)
        s += g_hg[i * H_DIM + f];
    sred[t] = s;
    __syncthreads();
    if (t < 64)
        sp[t] = (sred[t] + sred[t + 64] + sred[t + 128] + sred[t + 192]) *
                (1.0f / (float)N_NODES);
    __syncthreads();
    if (t < N_CLS) {
        float lg = 0.f;
        #pragma unroll 8
        for (int k = 0; k < 64; k++) lg += sp[k] * Wg2[k * N_CLS + t];
        slog[t] = lg;
    }
    __syncthreads();
    if (t < N_CLS) {
        float m = slog[0];
        #pragma unroll
        for (int cc = 1; cc < N_CLS; cc++) m = fmaxf(m, slog[cc]);
        sexp[t] = expf(slog[t] - m);
    }
    __syncthreads();
    if (t < N_CLS) {
        float sum = 0.f;
        #pragma unroll
        for (int cc = 0; cc < N_CLS; cc++) sum += sexp[cc];
        out[t] = sexp[t] / sum;
    }
}

// ---------------------------------------------------------------------------
extern "C" void kernel_launch(void* const* d_in, const int* in_sizes, int n_in,
                              void* d_out, int out_size)
{
    const float* x     = (const float*)d_in[0];
    const float* embed = (const float*)d_in[1];
    const float* adj   = (const float*)d_in[2];
    const float* tmp   = (const float*)d_in[3];
    const float* noise = (const float*)d_in[4];
    // d_in[5] = label (int), unused by the forward pass
    const float* W1    = (const float*)d_in[6];
    const float* b1    = (const float*)d_in[7];
    const float* W2    = (const float*)d_in[8];
    const float* b2    = (const float*)d_in[9];
    const float* Wg1   = (const float*)d_in[10];
    const float* Wg2   = (const float*)d_in[11];
    float* out = (float*)d_out;

    prep_kernel<<<128, 64>>>(embed, x, W1, b1, Wg1);
    edge_kernel<<<dim3(32, 32), 256>>>(noise, W2, b2, tmp);
    spmm_kernel<<<128, 256>>>(adj);
    final_kernel<<<1, 256>>>(Wg2, out);
}